// round 8
// baseline (speedup 1.0000x reference)
#include <cuda_runtime.h>

// Wilson Dslash, 32^4, DeGrand-Rossi, half-spinor trick.
// R8: R7 (x3 via warp shuffles) + __launch_bounds__(128,7) to raise the
// occupancy ceiling 24->28 warps; theory: L2 is at 78% busy but
// latency-limited by insufficient outstanding loads.

static constexpr int VOL = 1 << 20;

template<int A>
__device__ __forceinline__ void load9(const float* __restrict__ p, float* v) {
    if (A == 0) {
        float4 a = __ldg((const float4*)p);
        float4 b = __ldg((const float4*)(p + 4));
        v[0]=a.x; v[1]=a.y; v[2]=a.z; v[3]=a.w;
        v[4]=b.x; v[5]=b.y; v[6]=b.z; v[7]=b.w;
        v[8]=__ldg(p + 8);
    } else if (A == 4) {
        v[0]=__ldg(p);
        float2 c = __ldg((const float2*)(p + 1));
        float4 d = __ldg((const float4*)(p + 3));
        float2 e = __ldg((const float2*)(p + 7));
        v[1]=c.x; v[2]=c.y; v[3]=d.x; v[4]=d.y; v[5]=d.z; v[6]=d.w;
        v[7]=e.x; v[8]=e.y;
    } else if (A == 8) {
        float2 a = __ldg((const float2*)p);
        float4 b = __ldg((const float4*)(p + 2));
        float2 c = __ldg((const float2*)(p + 6));
        v[0]=a.x; v[1]=a.y; v[2]=b.x; v[3]=b.y; v[4]=b.z; v[5]=b.w;
        v[6]=c.x; v[7]=c.y; v[8]=__ldg(p + 8);
    } else {
        v[0]=__ldg(p);
        float4 b = __ldg((const float4*)(p + 1));
        float4 c = __ldg((const float4*)(p + 5));
        v[1]=b.x; v[2]=b.y; v[3]=b.z; v[4]=b.w;
        v[5]=c.x; v[6]=c.y; v[7]=c.z; v[8]=c.w;
    }
}

__device__ __forceinline__ void load12g(const float* __restrict__ p, float* v) {
    float4 a = __ldg((const float4*)p);
    float4 b = __ldg((const float4*)(p + 4));
    float4 c = __ldg((const float4*)(p + 8));
    v[0]=a.x; v[1]=a.y; v[2]=a.z;  v[3]=a.w;
    v[4]=b.x; v[5]=b.y; v[6]=b.z;  v[7]=b.w;
    v[8]=c.x; v[9]=c.y; v[10]=c.z; v[11]=c.w;
}

template<bool DAG>
__device__ __forceinline__ void matvec(
    const float* Ur, const float* Ui,
    const float* hr, const float* hi,
    float* gr, float* gi)
{
#pragma unroll
    for (int s = 0; s < 2; s++) {
#pragma unroll
        for (int i = 0; i < 3; i++) {
            float rr = 0.f, ii = 0.f;
#pragma unroll
            for (int j = 0; j < 3; j++) {
                float urv, uiv;
                if (!DAG) { urv = Ur[i * 3 + j]; uiv = Ui[i * 3 + j]; }
                else      { urv = Ur[j * 3 + i]; uiv = -Ui[j * 3 + i]; }
                rr += urv * hr[s * 3 + j] - uiv * hi[s * 3 + j];
                ii += urv * hi[s * 3 + j] + uiv * hr[s * 3 + j];
            }
            gr[s * 3 + i] = rr; gi[s * 3 + i] = ii;
        }
    }
}

template<int MU, bool DAG>
__device__ __forceinline__ void term_core(
    const float* Pr, const float* Pi,
    const float* __restrict__ ur, const float* __restrict__ ui,
    float* ar, float* ai)
{
    constexpr int A = (MU * 36) & 15;
    float Ur[9], Ui[9];
    load9<A>(ur, Ur);
    load9<A>(ui, Ui);

    float hr[6], hi[6];
#pragma unroll
    for (int c = 0; c < 3; c++) {
        float p0r = Pr[c],     p0i = Pi[c];
        float p1r = Pr[3 + c], p1i = Pi[3 + c];
        float p2r = Pr[6 + c], p2i = Pi[6 + c];
        float p3r = Pr[9 + c], p3i = Pi[9 + c];
        float h0r, h0i, h1r, h1i;
        if (MU == 0) {
            if (!DAG) { h0r = p0r + p3i; h0i = p0i - p3r; h1r = p1r + p2i; h1i = p1i - p2r; }
            else      { h0r = p0r - p3i; h0i = p0i + p3r; h1r = p1r - p2i; h1i = p1i + p2r; }
        } else if (MU == 1) {
            if (!DAG) { h0r = p0r + p3r; h0i = p0i + p3i; h1r = p1r - p2r; h1i = p1i - p2i; }
            else      { h0r = p0r - p3r; h0i = p0i - p3i; h1r = p1r + p2r; h1i = p1i + p2i; }
        } else {
            if (!DAG) { h0r = p0r + p2i; h0i = p0i - p2r; h1r = p1r - p3i; h1i = p1i + p3r; }
            else      { h0r = p0r - p2i; h0i = p0i + p2r; h1r = p1r + p3i; h1i = p1i - p3r; }
        }
        hr[c] = h0r; hi[c] = h0i; hr[3 + c] = h1r; hi[3 + c] = h1i;
    }

    float gr[6], gi[6];
    matvec<DAG>(Ur, Ui, hr, hi, gr, gi);

#pragma unroll
    for (int c = 0; c < 3; c++) {
        ar[c]     += gr[c];     ai[c]     += gi[c];
        ar[3 + c] += gr[3 + c]; ai[3 + c] += gi[3 + c];
        if (MU == 0) {
            if (!DAG) { ar[6+c] -= gi[3+c]; ai[6+c] += gr[3+c]; ar[9+c] -= gi[c]; ai[9+c] += gr[c]; }
            else      { ar[6+c] += gi[3+c]; ai[6+c] -= gr[3+c]; ar[9+c] += gi[c]; ai[9+c] -= gr[c]; }
        } else if (MU == 1) {
            if (!DAG) { ar[6+c] -= gr[3+c]; ai[6+c] -= gi[3+c]; ar[9+c] += gr[c]; ai[9+c] += gi[c]; }
            else      { ar[6+c] += gr[3+c]; ai[6+c] += gi[3+c]; ar[9+c] -= gr[c]; ai[9+c] -= gi[c]; }
        } else {
            if (!DAG) { ar[6+c] -= gi[c]; ai[6+c] += gr[c]; ar[9+c] += gi[3+c]; ai[9+c] -= gr[3+c]; }
            else      { ar[6+c] += gi[c]; ai[6+c] -= gr[c]; ar[9+c] -= gi[3+c]; ai[9+c] += gr[3+c]; }
        }
    }
}

__global__ void __launch_bounds__(128, 7) wilson_dslash_kernel(
    const float* __restrict__ psi_re, const float* __restrict__ psi_im,
    const float* __restrict__ U_re,   const float* __restrict__ U_im,
    float* __restrict__ out_re, float* __restrict__ out_im)
{
    const int site = blockIdx.x * blockDim.x + threadIdx.x;
    const int lane = threadIdx.x & 31;     // = x3 (warp is one periodic x3 line)
    const int x2 = (site >> 5) & 31, x1 = (site >> 10) & 31, x0 = site >> 15;
    const unsigned FULL = 0xffffffffu;
    const int upLane = (lane + 1) & 31;
    const int dnLane = (lane + 31) & 31;

    float ar[12], ai[12];
#pragma unroll
    for (int k = 0; k < 12; k++) { ar[k] = 0.f; ai[k] = 0.f; }

    const size_t s36 = (size_t)site * 36;

    // ================= mu = 3 via warp shuffles =================
    {
        float Or[12], Oi[12];
        load12g(psi_re + (size_t)site * 12, Or);
        load12g(psi_im + (size_t)site * 12, Oi);
        float U3r[9], U3i[9];
        load9<12>(U_re + s36 + 27, U3r);
        load9<12>(U_im + s36 + 27, U3i);

        float hr[6], hi[6];
#pragma unroll
        for (int c = 0; c < 3; c++) {
            hr[c]     = Or[c]     - Or[6 + c];  hi[c]     = Oi[c]     - Oi[6 + c];
            hr[3 + c] = Or[3 + c] - Or[9 + c];  hi[3 + c] = Oi[3 + c] - Oi[9 + c];
        }
#pragma unroll
        for (int k = 0; k < 6; k++) {
            hr[k] = __shfl_sync(FULL, hr[k], upLane, 32);
            hi[k] = __shfl_sync(FULL, hi[k], upLane, 32);
        }
        float gr[6], gi[6];
        matvec<false>(U3r, U3i, hr, hi, gr, gi);
#pragma unroll
        for (int c = 0; c < 3; c++) {
            ar[c]     += gr[c];     ai[c]     += gi[c];
            ar[3 + c] += gr[3 + c]; ai[3 + c] += gi[3 + c];
            ar[6 + c] -= gr[c];     ai[6 + c] -= gi[c];
            ar[9 + c] -= gr[3 + c]; ai[9 + c] -= gi[3 + c];
        }

#pragma unroll
        for (int c = 0; c < 3; c++) {
            hr[c]     = Or[c]     + Or[6 + c];  hi[c]     = Oi[c]     + Oi[6 + c];
            hr[3 + c] = Or[3 + c] + Or[9 + c];  hi[3 + c] = Oi[3 + c] + Oi[9 + c];
        }
        matvec<true>(U3r, U3i, hr, hi, gr, gi);
#pragma unroll
        for (int k = 0; k < 6; k++) {
            gr[k] = __shfl_sync(FULL, gr[k], dnLane, 32);
            gi[k] = __shfl_sync(FULL, gi[k], dnLane, 32);
        }
#pragma unroll
        for (int c = 0; c < 3; c++) {
            ar[c]     += gr[c];     ai[c]     += gi[c];
            ar[3 + c] += gr[3 + c]; ai[3 + c] += gi[3 + c];
            ar[6 + c] += gr[c];     ai[6 + c] += gi[c];
            ar[9 + c] += gr[3 + c]; ai[9 + c] += gi[3 + c];
        }
    }

    // ================= mu = 0,1,2 via global loads =================
    const int fw0 = (x0 == 31) ? site - (31 << 15) : site + (1 << 15);
    const int bw0 = (x0 == 0)  ? site + (31 << 15) : site - (1 << 15);
    const int fw1 = (x1 == 31) ? site - (31 << 10) : site + (1 << 10);
    const int bw1 = (x1 == 0)  ? site + (31 << 10) : site - (1 << 10);
    const int fw2 = (x2 == 31) ? site - (31 << 5)  : site + (1 << 5);
    const int bw2 = (x2 == 0)  ? site + (31 << 5)  : site - (1 << 5);

    float Pr[12], Pi[12];

    load12g(psi_re + (size_t)fw0 * 12, Pr); load12g(psi_im + (size_t)fw0 * 12, Pi);
    term_core<0, false>(Pr, Pi, U_re + s36, U_im + s36, ar, ai);
    load12g(psi_re + (size_t)bw0 * 12, Pr); load12g(psi_im + (size_t)bw0 * 12, Pi);
    term_core<0, true >(Pr, Pi, U_re + (size_t)bw0 * 36, U_im + (size_t)bw0 * 36, ar, ai);

    load12g(psi_re + (size_t)fw1 * 12, Pr); load12g(psi_im + (size_t)fw1 * 12, Pi);
    term_core<1, false>(Pr, Pi, U_re + s36 + 9, U_im + s36 + 9, ar, ai);
    load12g(psi_re + (size_t)bw1 * 12, Pr); load12g(psi_im + (size_t)bw1 * 12, Pi);
    term_core<1, true >(Pr, Pi, U_re + (size_t)bw1 * 36 + 9, U_im + (size_t)bw1 * 36 + 9, ar, ai);

    load12g(psi_re + (size_t)fw2 * 12, Pr); load12g(psi_im + (size_t)fw2 * 12, Pi);
    term_core<2, false>(Pr, Pi, U_re + s36 + 18, U_im + s36 + 18, ar, ai);
    load12g(psi_re + (size_t)bw2 * 12, Pr); load12g(psi_im + (size_t)bw2 * 12, Pi);
    term_core<2, true >(Pr, Pi, U_re + (size_t)bw2 * 36 + 18, U_im + (size_t)bw2 * 36 + 18, ar, ai);

    size_t o = (size_t)site * 12;
    float4 v;
    v.x = -0.5f * ar[0]; v.y = -0.5f * ar[1]; v.z = -0.5f * ar[2];  v.w = -0.5f * ar[3];
    *(float4*)(out_re + o)     = v;
    v.x = -0.5f * ar[4]; v.y = -0.5f * ar[5]; v.z = -0.5f * ar[6];  v.w = -0.5f * ar[7];
    *(float4*)(out_re + o + 4) = v;
    v.x = -0.5f * ar[8]; v.y = -0.5f * ar[9]; v.z = -0.5f * ar[10]; v.w = -0.5f * ar[11];
    *(float4*)(out_re + o + 8) = v;
    v.x = -0.5f * ai[0]; v.y = -0.5f * ai[1]; v.z = -0.5f * ai[2];  v.w = -0.5f * ai[3];
    *(float4*)(out_im + o)     = v;
    v.x = -0.5f * ai[4]; v.y = -0.5f * ai[5]; v.z = -0.5f * ai[6];  v.w = -0.5f * ai[7];
    *(float4*)(out_im + o + 4) = v;
    v.x = -0.5f * ai[8]; v.y = -0.5f * ai[9]; v.z = -0.5f * ai[10]; v.w = -0.5f * ai[11];
    *(float4*)(out_im + o + 8) = v;
}

extern "C" void kernel_launch(void* const* d_in, const int* in_sizes, int n_in,
                              void* d_out, int out_size) {
    const float* psi_re = (const float*)d_in[0];
    const float* psi_im = (const float*)d_in[1];
    const float* U_re   = (const float*)d_in[2];
    const float* U_im   = (const float*)d_in[3];
    float* out = (float*)d_out;
    float* out_re = out;
    float* out_im = out + (size_t)VOL * 12;

    wilson_dslash_kernel<<<VOL / 128, 128>>>(psi_re, psi_im, U_re, U_im, out_re, out_im);
}

// round 14
// speedup vs baseline: 1.2078x; 1.2078x over previous
#include <cuda_runtime.h>

// Wilson Dslash, 32^4, DeGrand-Rossi, half-spinor trick.
// R14 (= R9 resubmit; five consecutive GPU-acquisition infra failures):
// x0-pair thread coarsening. Each thread does sites (2k, 2k+1) along x0:
//   psi[s0]/psi[s1] serve as each other's x0-neighbors (register reuse),
//   U0[s0] serves fw(s0) and bw(s1). Cuts ~130B/site of true L2-miss traffic.
// x3 direction still via warp shuffles (R7).

static constexpr int VOL = 1 << 20;

template<int A>
__device__ __forceinline__ void load9(const float* __restrict__ p, float* v) {
    if (A == 0) {
        float4 a = __ldg((const float4*)p);
        float4 b = __ldg((const float4*)(p + 4));
        v[0]=a.x; v[1]=a.y; v[2]=a.z; v[3]=a.w;
        v[4]=b.x; v[5]=b.y; v[6]=b.z; v[7]=b.w;
        v[8]=__ldg(p + 8);
    } else if (A == 4) {
        v[0]=__ldg(p);
        float2 c = __ldg((const float2*)(p + 1));
        float4 d = __ldg((const float4*)(p + 3));
        float2 e = __ldg((const float2*)(p + 7));
        v[1]=c.x; v[2]=c.y; v[3]=d.x; v[4]=d.y; v[5]=d.z; v[6]=d.w;
        v[7]=e.x; v[8]=e.y;
    } else if (A == 8) {
        float2 a = __ldg((const float2*)p);
        float4 b = __ldg((const float4*)(p + 2));
        float2 c = __ldg((const float2*)(p + 6));
        v[0]=a.x; v[1]=a.y; v[2]=b.x; v[3]=b.y; v[4]=b.z; v[5]=b.w;
        v[6]=c.x; v[7]=c.y; v[8]=__ldg(p + 8);
    } else {
        v[0]=__ldg(p);
        float4 b = __ldg((const float4*)(p + 1));
        float4 c = __ldg((const float4*)(p + 5));
        v[1]=b.x; v[2]=b.y; v[3]=b.z; v[4]=b.w;
        v[5]=c.x; v[6]=c.y; v[7]=c.z; v[8]=c.w;
    }
}

__device__ __forceinline__ void load12g(const float* __restrict__ p, float* v) {
    float4 a = __ldg((const float4*)p);
    float4 b = __ldg((const float4*)(p + 4));
    float4 c = __ldg((const float4*)(p + 8));
    v[0]=a.x; v[1]=a.y; v[2]=a.z;  v[3]=a.w;
    v[4]=b.x; v[5]=b.y; v[6]=b.z;  v[7]=b.w;
    v[8]=c.x; v[9]=c.y; v[10]=c.z; v[11]=c.w;
}

template<bool DAG>
__device__ __forceinline__ void matvec(
    const float* Ur, const float* Ui,
    const float* hr, const float* hi,
    float* gr, float* gi)
{
#pragma unroll
    for (int s = 0; s < 2; s++) {
#pragma unroll
        for (int i = 0; i < 3; i++) {
            float rr = 0.f, ii = 0.f;
#pragma unroll
            for (int j = 0; j < 3; j++) {
                float urv, uiv;
                if (!DAG) { urv = Ur[i * 3 + j]; uiv = Ui[i * 3 + j]; }
                else      { urv = Ur[j * 3 + i]; uiv = -Ui[j * 3 + i]; }
                rr += urv * hr[s * 3 + j] - uiv * hi[s * 3 + j];
                ii += urv * hi[s * 3 + j] + uiv * hr[s * 3 + j];
            }
            gr[s * 3 + i] = rr; gi[s * 3 + i] = ii;
        }
    }
}

// Reconstruction for mu=0.
template<bool DAG>
__device__ __forceinline__ void recon0(const float* gr, const float* gi, float* ar, float* ai) {
#pragma unroll
    for (int c = 0; c < 3; c++) {
        ar[c]     += gr[c];     ai[c]     += gi[c];
        ar[3 + c] += gr[3 + c]; ai[3 + c] += gi[3 + c];
        if (!DAG) { ar[6+c] -= gi[3+c]; ai[6+c] += gr[3+c]; ar[9+c] -= gi[c]; ai[9+c] += gr[c]; }
        else      { ar[6+c] += gi[3+c]; ai[6+c] -= gr[3+c]; ar[9+c] += gi[c]; ai[9+c] -= gr[c]; }
    }
}

// Generic term for mu = 0,1,2 (psi preloaded in Pr/Pi).
template<int MU, bool DAG>
__device__ __forceinline__ void term_core(
    const float* Pr, const float* Pi,
    const float* __restrict__ ur, const float* __restrict__ ui,
    float* ar, float* ai)
{
    constexpr int A = (MU * 36) & 15;
    float Ur[9], Ui[9];
    load9<A>(ur, Ur);
    load9<A>(ui, Ui);

    float hr[6], hi[6];
#pragma unroll
    for (int c = 0; c < 3; c++) {
        float p0r = Pr[c],     p0i = Pi[c];
        float p1r = Pr[3 + c], p1i = Pi[3 + c];
        float p2r = Pr[6 + c], p2i = Pi[6 + c];
        float p3r = Pr[9 + c], p3i = Pi[9 + c];
        float h0r, h0i, h1r, h1i;
        if (MU == 0) {
            if (!DAG) { h0r = p0r + p3i; h0i = p0i - p3r; h1r = p1r + p2i; h1i = p1i - p2r; }
            else      { h0r = p0r - p3i; h0i = p0i + p3r; h1r = p1r - p2i; h1i = p1i + p2r; }
        } else if (MU == 1) {
            if (!DAG) { h0r = p0r + p3r; h0i = p0i + p3i; h1r = p1r - p2r; h1i = p1i - p2i; }
            else      { h0r = p0r - p3r; h0i = p0i - p3i; h1r = p1r + p2r; h1i = p1i + p2i; }
        } else {
            if (!DAG) { h0r = p0r + p2i; h0i = p0i - p2r; h1r = p1r - p3i; h1i = p1i + p3r; }
            else      { h0r = p0r - p2i; h0i = p0i + p2r; h1r = p1r + p3i; h1i = p1i - p3r; }
        }
        hr[c] = h0r; hi[c] = h0i; hr[3 + c] = h1r; hi[3 + c] = h1i;
    }

    float gr[6], gi[6];
    matvec<DAG>(Ur, Ui, hr, hi, gr, gi);

#pragma unroll
    for (int c = 0; c < 3; c++) {
        ar[c]     += gr[c];     ai[c]     += gi[c];
        ar[3 + c] += gr[3 + c]; ai[3 + c] += gi[3 + c];
        if (MU == 0) {
            if (!DAG) { ar[6+c] -= gi[3+c]; ai[6+c] += gr[3+c]; ar[9+c] -= gi[c]; ai[9+c] += gr[c]; }
            else      { ar[6+c] += gi[3+c]; ai[6+c] -= gr[3+c]; ar[9+c] += gi[c]; ai[9+c] -= gr[c]; }
        } else if (MU == 1) {
            if (!DAG) { ar[6+c] -= gr[3+c]; ai[6+c] -= gi[3+c]; ar[9+c] += gr[c]; ai[9+c] += gi[c]; }
            else      { ar[6+c] += gr[3+c]; ai[6+c] += gi[3+c]; ar[9+c] -= gr[c]; ai[9+c] -= gi[c]; }
        } else {
            if (!DAG) { ar[6+c] -= gi[c]; ai[6+c] += gr[c]; ar[9+c] += gi[3+c]; ai[9+c] -= gr[3+c]; }
            else      { ar[6+c] += gi[c]; ai[6+c] -= gr[c]; ar[9+c] -= gi[3+c]; ai[9+c] += gr[3+c]; }
        }
    }
}

// mu=3 both directions via warp shuffles (warp = periodic x3 line). Own psi in Or/Oi.
__device__ __forceinline__ void mu3_term(
    const float* Or, const float* Oi,
    const float* __restrict__ u3r, const float* __restrict__ u3i,
    int upLane, int dnLane, float* ar, float* ai)
{
    const unsigned FULL = 0xffffffffu;
    float U3r[9], U3i[9];
    load9<12>(u3r, U3r);
    load9<12>(u3i, U3i);

    float hr[6], hi[6], gr[6], gi[6];
    // forward: neighbor's proj_m3
#pragma unroll
    for (int c = 0; c < 3; c++) {
        hr[c]     = Or[c]     - Or[6 + c];  hi[c]     = Oi[c]     - Oi[6 + c];
        hr[3 + c] = Or[3 + c] - Or[9 + c];  hi[3 + c] = Oi[3 + c] - Oi[9 + c];
    }
#pragma unroll
    for (int k = 0; k < 6; k++) {
        hr[k] = __shfl_sync(FULL, hr[k], upLane, 32);
        hi[k] = __shfl_sync(FULL, hi[k], upLane, 32);
    }
    matvec<false>(U3r, U3i, hr, hi, gr, gi);
#pragma unroll
    for (int c = 0; c < 3; c++) {
        ar[c]     += gr[c];     ai[c]     += gi[c];
        ar[3 + c] += gr[3 + c]; ai[3 + c] += gi[3 + c];
        ar[6 + c] -= gr[c];     ai[6 + c] -= gi[c];
        ar[9 + c] -= gr[3 + c]; ai[9 + c] -= gi[3 + c];
    }
    // backward: x-3 thread computes full U^dag * proj_p3 product, shuffle result
#pragma unroll
    for (int c = 0; c < 3; c++) {
        hr[c]     = Or[c]     + Or[6 + c];  hi[c]     = Oi[c]     + Oi[6 + c];
        hr[3 + c] = Or[3 + c] + Or[9 + c];  hi[3 + c] = Oi[3 + c] + Oi[9 + c];
    }
    matvec<true>(U3r, U3i, hr, hi, gr, gi);
#pragma unroll
    for (int k = 0; k < 6; k++) {
        gr[k] = __shfl_sync(FULL, gr[k], dnLane, 32);
        gi[k] = __shfl_sync(FULL, gi[k], dnLane, 32);
    }
#pragma unroll
    for (int c = 0; c < 3; c++) {
        ar[c]     += gr[c];     ai[c]     += gi[c];
        ar[3 + c] += gr[3 + c]; ai[3 + c] += gi[3 + c];
        ar[6 + c] += gr[c];     ai[6 + c] += gi[c];
        ar[9 + c] += gr[3 + c]; ai[9 + c] += gi[3 + c];
    }
}

// mu=1,2 terms for a site + store.
__device__ __forceinline__ void finish_site(
    int site, int x1, int x2,
    const float* __restrict__ psi_re, const float* __restrict__ psi_im,
    const float* __restrict__ U_re,   const float* __restrict__ U_im,
    float* __restrict__ out_re, float* __restrict__ out_im,
    float* ar, float* ai)
{
    const size_t s36 = (size_t)site * 36;
    const int fw1 = (x1 == 31) ? site - (31 << 10) : site + (1 << 10);
    const int bw1 = (x1 == 0)  ? site + (31 << 10) : site - (1 << 10);
    const int fw2 = (x2 == 31) ? site - (31 << 5)  : site + (1 << 5);
    const int bw2 = (x2 == 0)  ? site + (31 << 5)  : site - (1 << 5);

    float Pr[12], Pi[12];
    load12g(psi_re + (size_t)fw1 * 12, Pr); load12g(psi_im + (size_t)fw1 * 12, Pi);
    term_core<1, false>(Pr, Pi, U_re + s36 + 9, U_im + s36 + 9, ar, ai);
    load12g(psi_re + (size_t)bw1 * 12, Pr); load12g(psi_im + (size_t)bw1 * 12, Pi);
    term_core<1, true >(Pr, Pi, U_re + (size_t)bw1 * 36 + 9, U_im + (size_t)bw1 * 36 + 9, ar, ai);

    load12g(psi_re + (size_t)fw2 * 12, Pr); load12g(psi_im + (size_t)fw2 * 12, Pi);
    term_core<2, false>(Pr, Pi, U_re + s36 + 18, U_im + s36 + 18, ar, ai);
    load12g(psi_re + (size_t)bw2 * 12, Pr); load12g(psi_im + (size_t)bw2 * 12, Pi);
    term_core<2, true >(Pr, Pi, U_re + (size_t)bw2 * 36 + 18, U_im + (size_t)bw2 * 36 + 18, ar, ai);

    size_t o = (size_t)site * 12;
    float4 v;
    v.x = -0.5f * ar[0]; v.y = -0.5f * ar[1]; v.z = -0.5f * ar[2];  v.w = -0.5f * ar[3];
    *(float4*)(out_re + o)     = v;
    v.x = -0.5f * ar[4]; v.y = -0.5f * ar[5]; v.z = -0.5f * ar[6];  v.w = -0.5f * ar[7];
    *(float4*)(out_re + o + 4) = v;
    v.x = -0.5f * ar[8]; v.y = -0.5f * ar[9]; v.z = -0.5f * ar[10]; v.w = -0.5f * ar[11];
    *(float4*)(out_re + o + 8) = v;
    v.x = -0.5f * ai[0]; v.y = -0.5f * ai[1]; v.z = -0.5f * ai[2];  v.w = -0.5f * ai[3];
    *(float4*)(out_im + o)     = v;
    v.x = -0.5f * ai[4]; v.y = -0.5f * ai[5]; v.z = -0.5f * ai[6];  v.w = -0.5f * ai[7];
    *(float4*)(out_im + o + 4) = v;
    v.x = -0.5f * ai[8]; v.y = -0.5f * ai[9]; v.z = -0.5f * ai[10]; v.w = -0.5f * ai[11];
    *(float4*)(out_im + o + 8) = v;
}

__global__ void __launch_bounds__(128, 4) wilson_dslash_kernel(
    const float* __restrict__ psi_re, const float* __restrict__ psi_im,
    const float* __restrict__ U_re,   const float* __restrict__ U_im,
    float* __restrict__ out_re, float* __restrict__ out_im)
{
    const int idx = blockIdx.x * blockDim.x + threadIdx.x;   // VOL/2 threads
    const int lane = threadIdx.x & 31;
    const int upLane = (lane + 1) & 31;
    const int dnLane = (lane + 31) & 31;

    const int x2 = (idx >> 5) & 31, x1 = (idx >> 10) & 31, x0p = idx >> 15;  // x0p: 0..15
    const int x0a = x0p << 1;                 // even x0
    const int s0 = (x0a << 15) | (idx & 0x7FFF);
    const int s1 = s0 + (1 << 15);

    // Pair-shared loads
    float P0r[12], P0i[12], P1r[12], P1i[12];
    load12g(psi_re + (size_t)s0 * 12, P0r); load12g(psi_im + (size_t)s0 * 12, P0i);
    load12g(psi_re + (size_t)s1 * 12, P1r); load12g(psi_im + (size_t)s1 * 12, P1i);

    float ar[12], ai[12];
#pragma unroll
    for (int k = 0; k < 12; k++) { ar[k] = 0.f; ai[k] = 0.f; }

    float c1r[6], c1i[6];   // carry: bw-mu0 matvec result for s1
    {
        float Ur[9], Ui[9];
        load9<0>(U_re + (size_t)s0 * 36, Ur);
        load9<0>(U_im + (size_t)s0 * 36, Ui);

        // fw(s0): proj_m0(psi[s1]), U0[s0] * h  -> acc(s0)
        float hr[6], hi[6], gr[6], gi[6];
#pragma unroll
        for (int c = 0; c < 3; c++) {
            hr[c]     = P1r[c]     + P1i[9 + c];  hi[c]     = P1i[c]     - P1r[9 + c];
            hr[3 + c] = P1r[3 + c] + P1i[6 + c];  hi[3 + c] = P1i[3 + c] - P1r[6 + c];
        }
        matvec<false>(Ur, Ui, hr, hi, gr, gi);
        recon0<false>(gr, gi, ar, ai);

        // bw(s1): proj_p0(psi[s0]), U0[s0]^dag * h -> carry for s1
#pragma unroll
        for (int c = 0; c < 3; c++) {
            hr[c]     = P0r[c]     - P0i[9 + c];  hi[c]     = P0i[c]     + P0r[9 + c];
            hr[3 + c] = P0r[3 + c] - P0i[6 + c];  hi[3 + c] = P0i[3 + c] + P0r[6 + c];
        }
        matvec<true>(Ur, Ui, hr, hi, c1r, c1i);
    }

    // ---- site s0 ----
    mu3_term(P0r, P0i, U_re + (size_t)s0 * 36 + 27, U_im + (size_t)s0 * 36 + 27,
             upLane, dnLane, ar, ai);

    {   // mu0 backward for s0 (remote load)
        const int bw0 = (x0a == 0) ? s0 + (31 << 15) : s0 - (1 << 15);
        float Pr[12], Pi[12];
        load12g(psi_re + (size_t)bw0 * 12, Pr); load12g(psi_im + (size_t)bw0 * 12, Pi);
        term_core<0, true>(Pr, Pi, U_re + (size_t)bw0 * 36, U_im + (size_t)bw0 * 36, ar, ai);
    }
    finish_site(s0, x1, x2, psi_re, psi_im, U_re, U_im, out_re, out_im, ar, ai);

    // ---- site s1 ----
#pragma unroll
    for (int k = 0; k < 12; k++) { ar[k] = 0.f; ai[k] = 0.f; }
    recon0<true>(c1r, c1i, ar, ai);   // the carried bw-mu0 term

    mu3_term(P1r, P1i, U_re + (size_t)s1 * 36 + 27, U_im + (size_t)s1 * 36 + 27,
             upLane, dnLane, ar, ai);

    {   // mu0 forward for s1 (remote load)
        const int fw0 = (x0a + 1 == 31) ? s1 - (31 << 15) : s1 + (1 << 15);
        float Pr[12], Pi[12];
        load12g(psi_re + (size_t)fw0 * 12, Pr); load12g(psi_im + (size_t)fw0 * 12, Pi);
        term_core<0, false>(Pr, Pi, U_re + (size_t)s1 * 36, U_im + (size_t)s1 * 36, ar, ai);
    }
    finish_site(s1, x1, x2, psi_re, psi_im, U_re, U_im, out_re, out_im, ar, ai);
}

extern "C" void kernel_launch(void* const* d_in, const int* in_sizes, int n_in,
                              void* d_out, int out_size) {
    const float* psi_re = (const float*)d_in[0];
    const float* psi_im = (const float*)d_in[1];
    const float* U_re   = (const float*)d_in[2];
    const float* U_im   = (const float*)d_in[3];
    float* out = (float*)d_out;
    float* out_re = out;
    float* out_im = out + (size_t)VOL * 12;

    wilson_dslash_kernel<<<(VOL / 2) / 128, 128>>>(psi_re, psi_im, U_re, U_im, out_re, out_im);
}